// round 1
// baseline (speedup 1.0000x reference)
#include <cuda_runtime.h>

#define BB 2
#define SEQL 2048
#define DD 256
#define HH 8
#define DKK 32
#define DFFN 1024
#define LL 2
#define EPSF 1e-5f

#define NH  (BB*SEQL*DD)      /* 1048576 */
#define NFF (BB*SEQL*DFFN)    /* 4194304 */

// scratch: H0, H2, Q, K, V, CTX, T (each NH), FF (NFF), TAIL(512), smalls(8192)
__device__ float g_buf[7L*NH + NFF + 512 + 8192];

__device__ __forceinline__ int compute_kcut(float tdh) {
    if (!(tdh > 1e-6f)) return SEQL;
    float c = 128.0f / tdh;
    if (c >= (float)SEQL) return SEQL;
    int k = (int)ceilf(c);
    return k < SEQL ? k : SEQL;
}

// ---------------------------------------------------------------- conv + bn + relu + pe
__global__ void conv_pe_kernel(const float* __restrict__ x, const float* __restrict__ cw,
                               const float* __restrict__ cb, const float* __restrict__ bg,
                               const float* __restrict__ bb, const float* __restrict__ pe,
                               float* __restrict__ out) {
    int idx = blockIdx.x * 256 + threadIdx.x;
    if (idx >= NH) return;
    int d = idx & (DD - 1);
    int t = (idx >> 8) & (SEQL - 1);
    int b = idx >> 19;
    const float* xb = x + b * SEQL;
    float xm = t > 0 ? xb[t - 1] : 0.f;
    float x0 = xb[t];
    float xp = (t < SEQL - 1) ? xb[t + 1] : 0.f;
    float v = cw[d * 3 + 0] * xm + cw[d * 3 + 1] * x0 + cw[d * 3 + 2] * xp + cb[d];
    v = v * rsqrtf(1.f + EPSF) * bg[d] + bb[d];
    v = fmaxf(v, 0.f);
    out[idx] = v + pe[t * DD + d];
}

// ---------------------------------------------------------------- tiled SGEMM: C = A(MxK) * W(NxK)^T + bias
template <bool RELU>
__global__ __launch_bounds__(256)
void gemm_kernel(const float* __restrict__ A, const float* __restrict__ W,
                 const float* __restrict__ bias, float* __restrict__ C,
                 int M, int N, int K) {
    __shared__ float As[16][66];
    __shared__ float Bs[16][66];
    int m0 = blockIdx.y * 64, n0 = blockIdx.x * 64;
    int tid = threadIdx.x;
    int lrow = tid >> 2, lq = tid & 3;        // load: row in tile, quad of k-chunk
    int ty = tid >> 4, tx = tid & 15;          // compute: 16x16 threads, 4x4 each
    int ty4 = ty * 4, tx4 = tx * 4;

    float acc[4][4];
#pragma unroll
    for (int i = 0; i < 4; i++)
#pragma unroll
        for (int j = 0; j < 4; j++) acc[i][j] = 0.f;

    for (int k0 = 0; k0 < K; k0 += 16) {
        float4 av = *(const float4*)(A + (long)(m0 + lrow) * K + k0 + lq * 4);
        float4 bv = *(const float4*)(W + (long)(n0 + lrow) * K + k0 + lq * 4);
        __syncthreads();
        As[lq * 4 + 0][lrow] = av.x; As[lq * 4 + 1][lrow] = av.y;
        As[lq * 4 + 2][lrow] = av.z; As[lq * 4 + 3][lrow] = av.w;
        Bs[lq * 4 + 0][lrow] = bv.x; Bs[lq * 4 + 1][lrow] = bv.y;
        Bs[lq * 4 + 2][lrow] = bv.z; Bs[lq * 4 + 3][lrow] = bv.w;
        __syncthreads();
#pragma unroll
        for (int kk = 0; kk < 16; ++kk) {
            float a0 = As[kk][ty4 + 0], a1 = As[kk][ty4 + 1];
            float a2 = As[kk][ty4 + 2], a3 = As[kk][ty4 + 3];
            float b0 = Bs[kk][tx4 + 0], b1 = Bs[kk][tx4 + 1];
            float b2 = Bs[kk][tx4 + 2], b3 = Bs[kk][tx4 + 3];
            acc[0][0] = fmaf(a0, b0, acc[0][0]); acc[0][1] = fmaf(a0, b1, acc[0][1]);
            acc[0][2] = fmaf(a0, b2, acc[0][2]); acc[0][3] = fmaf(a0, b3, acc[0][3]);
            acc[1][0] = fmaf(a1, b0, acc[1][0]); acc[1][1] = fmaf(a1, b1, acc[1][1]);
            acc[1][2] = fmaf(a1, b2, acc[1][2]); acc[1][3] = fmaf(a1, b3, acc[1][3]);
            acc[2][0] = fmaf(a2, b0, acc[2][0]); acc[2][1] = fmaf(a2, b1, acc[2][1]);
            acc[2][2] = fmaf(a2, b2, acc[2][2]); acc[2][3] = fmaf(a2, b3, acc[2][3]);
            acc[3][0] = fmaf(a3, b0, acc[3][0]); acc[3][1] = fmaf(a3, b1, acc[3][1]);
            acc[3][2] = fmaf(a3, b2, acc[3][2]); acc[3][3] = fmaf(a3, b3, acc[3][3]);
        }
    }
    float bsv0 = bias[n0 + tx4 + 0], bsv1 = bias[n0 + tx4 + 1];
    float bsv2 = bias[n0 + tx4 + 2], bsv3 = bias[n0 + tx4 + 3];
#pragma unroll
    for (int i = 0; i < 4; ++i) {
        float4 v;
        v.x = acc[i][0] + bsv0; v.y = acc[i][1] + bsv1;
        v.z = acc[i][2] + bsv2; v.w = acc[i][3] + bsv3;
        if (RELU) {
            v.x = fmaxf(v.x, 0.f); v.y = fmaxf(v.y, 0.f);
            v.z = fmaxf(v.z, 0.f); v.w = fmaxf(v.w, 0.f);
        }
        *(float4*)(C + (long)(m0 + ty4 + i) * N + n0 + tx4) = v;
    }
}

// ---------------------------------------------------------------- tail-V: sum_{k>=kcut} v[b,k,h*32+d]
__global__ void tailv_kernel(const float* __restrict__ V, const float* __restrict__ td,
                             float* __restrict__ tailV, int l) {
    int b = blockIdx.x / HH, h = blockIdx.x % HH;
    float tdh = td[l * HH + h];
    int kcut = compute_kcut(tdh);
    int d = threadIdx.x & 31, kg = threadIdx.x >> 5;
    float s = 0.f;
    for (int k = kcut + kg; k < SEQL; k += 8)
        s += V[((long)(b * SEQL + k)) * DD + h * DKK + d];
    __shared__ float sm[8][32];
    sm[kg][d] = s;
    __syncthreads();
    if (kg == 0) {
        float t = 0.f;
#pragma unroll
        for (int i = 0; i < 8; i++) t += sm[i][d];
        tailV[blockIdx.x * DKK + d] = t;
    }
}

// ---------------------------------------------------------------- attention (all queries), kcut-truncated
__global__ __launch_bounds__(128)
void attn_kernel(const float* __restrict__ Q, const float* __restrict__ Km,
                 const float* __restrict__ Vm, const float* __restrict__ td,
                 const float* __restrict__ scale, const float* __restrict__ tailV,
                 float* __restrict__ ctx, int l) {
    __shared__ float Ks[128][DKK];
    __shared__ float Vs[128][DKK];
    __shared__ float dec[128];
    int bh = blockIdx.y;
    int b = bh / HH, h = bh % HH;
    int tid = threadIdx.x;
    int q = blockIdx.x * 128 + tid;
    float tdh = td[l * HH + h];
    int kcut = compute_kcut(tdh);
    float c = scale[l] * rsqrtf((float)DKK);
    float qr[DKK];
    {
        const float* qp = Q + ((long)(b * SEQL + q)) * DD + h * DKK;
#pragma unroll
        for (int d = 0; d < DKK; ++d) qr[d] = qp[d] * c;
    }
    float Z = 0.f;
    float cx[DKK];
#pragma unroll
    for (int d = 0; d < DKK; ++d) cx[d] = 0.f;

    for (int kb = 0; kb < kcut; kb += 128) {
        int kn = min(128, kcut - kb);
        __syncthreads();
        long base = ((long)(b * SEQL + kb)) * DD + h * DKK;
#pragma unroll
        for (int i = 0; i < 32; i++) {
            int idx = i * 128 + tid;
            int r = idx >> 5, cc = idx & 31;
            if (r < kn) {
                Ks[r][cc] = Km[base + (long)r * DD + cc];
                Vs[r][cc] = Vm[base + (long)r * DD + cc];
            }
        }
        if (tid < kn) dec[tid] = expf(-tdh * (float)(kb + tid));
        __syncthreads();
        for (int kk = 0; kk < kn; ++kk) {
            float s0 = 0.f, s1 = 0.f, s2 = 0.f, s3 = 0.f;
#pragma unroll
            for (int d = 0; d < DKK; d += 4) {
                s0 = fmaf(qr[d + 0], Ks[kk][d + 0], s0);
                s1 = fmaf(qr[d + 1], Ks[kk][d + 1], s1);
                s2 = fmaf(qr[d + 2], Ks[kk][d + 2], s2);
                s3 = fmaf(qr[d + 3], Ks[kk][d + 3], s3);
            }
            float s = ((s0 + s1) + (s2 + s3)) * dec[kk];
            float e = expf(s);
            float w = e / (1.f + expf(-s));
            Z += e;
#pragma unroll
            for (int d = 0; d < DKK; ++d) cx[d] = fmaf(w, Vs[kk][d], cx[d]);
        }
    }
    Z += (float)(SEQL - kcut);
    float invZ = 1.f / Z;
    const float* tv = tailV + bh * DKK;
    float* op = ctx + ((long)(b * SEQL + q)) * DD + h * DKK;
#pragma unroll
    for (int d = 0; d < DKK; ++d) op[d] = (cx[d] + 0.5f * tv[d]) * invZ;
}

// ---------------------------------------------------------------- single-query attention (layer 2 last token)
__global__ __launch_bounds__(128)
void attn1_kernel(const float* __restrict__ q2, const float* __restrict__ Km,
                  const float* __restrict__ Vm, const float* __restrict__ td,
                  const float* __restrict__ scale, const float* __restrict__ tailV,
                  float* __restrict__ ctx2, int l) {
    int b = blockIdx.x / HH, h = blockIdx.x % HH;
    int tid = threadIdx.x;
    float tdh = td[l * HH + h];
    int kcut = compute_kcut(tdh);
    float c = scale[l] * rsqrtf((float)DKK);
    __shared__ float qs[DKK];
    __shared__ float ws[128];
    __shared__ float red[4];
    if (tid < DKK) qs[tid] = q2[b * DD + h * DKK + tid] * c;
    __syncthreads();
    float Zp = 0.f;
    float cxd = 0.f;
    for (int kb = 0; kb < kcut; kb += 128) {
        int kn = min(128, kcut - kb);
        float w = 0.f;
        if (tid < kn) {
            int k = kb + tid;
            const float* kr = Km + ((long)(b * SEQL + k)) * DD + h * DKK;
            float s = 0.f;
#pragma unroll
            for (int d = 0; d < DKK; ++d) s = fmaf(qs[d], kr[d], s);
            s *= expf(-tdh * (float)k);
            float e = expf(s);
            w = e / (1.f + expf(-s));
            Zp += e;
        }
        __syncthreads();
        ws[tid] = w;
        __syncthreads();
        if (tid < DKK) {
            for (int kk = 0; kk < kn; ++kk)
                cxd = fmaf(ws[kk], Vm[((long)(b * SEQL + kb + kk)) * DD + h * DKK + tid], cxd);
        }
        __syncthreads();
    }
    float s = Zp;
#pragma unroll
    for (int o = 16; o; o >>= 1) s += __shfl_xor_sync(0xffffffffu, s, o);
    if ((tid & 31) == 0) red[tid >> 5] = s;
    __syncthreads();
    float Z = red[0] + red[1] + red[2] + red[3] + (float)(SEQL - kcut);
    if (tid < DKK)
        ctx2[b * DD + h * DKK + tid] = (cxd + 0.5f * tailV[blockIdx.x * DKK + tid]) / Z;
}

// ---------------------------------------------------------------- small-M GEMM (M=2 rows)
template <bool RELU>
__global__ void rowgemm_kernel(const float* __restrict__ A, long lda,
                               const float* __restrict__ W, const float* __restrict__ bias,
                               float* __restrict__ C, int K, int N) {
    extern __shared__ float arow[];
    int m = blockIdx.x;
    int n = blockIdx.y * blockDim.x + threadIdx.x;
    for (int i = threadIdx.x; i < K; i += blockDim.x) arow[i] = A[(long)m * lda + i];
    __syncthreads();
    float s = bias[n];
    const float* wr = W + (long)n * K;
#pragma unroll 4
    for (int kk = 0; kk < K; ++kk) s = fmaf(arow[kk], wr[kk], s);
    if (RELU) s = fmaxf(s, 0.f);
    C[(long)m * N + n] = s;
}

// ---------------------------------------------------------------- residual + layernorm (one row per block, D=256)
__global__ void ln_kernel(const float* __restrict__ z, long zs,
                          const float* __restrict__ res, long rs,
                          const float* __restrict__ g, const float* __restrict__ be,
                          float* __restrict__ out, long os) {
    int m = blockIdx.x, t = threadIdx.x;
    float v = z[(long)m * zs + t] + res[(long)m * rs + t];
    __shared__ float sm[8];
    float s = v;
#pragma unroll
    for (int o = 16; o; o >>= 1) s += __shfl_xor_sync(0xffffffffu, s, o);
    if ((t & 31) == 0) sm[t >> 5] = s;
    __syncthreads();
    float tot = 0.f;
#pragma unroll
    for (int i = 0; i < 8; i++) tot += sm[i];
    float mean = tot * (1.0f / DD);
    float dv = v - mean;
    float s2 = dv * dv;
    __syncthreads();
#pragma unroll
    for (int o = 16; o; o >>= 1) s2 += __shfl_xor_sync(0xffffffffu, s2, o);
    if ((t & 31) == 0) sm[t >> 5] = s2;
    __syncthreads();
    float var = 0.f;
#pragma unroll
    for (int i = 0; i < 8; i++) var += sm[i];
    var *= (1.0f / DD);
    out[(long)m * os + t] = dv * rsqrtf(var + EPSF) * g[t] + be[t];
}

// ---------------------------------------------------------------- final projection: out[b] = 0.5 * dot(r2[b], outW) + outb
__global__ void out_kernel(const float* __restrict__ r2, const float* __restrict__ ow,
                           const float* __restrict__ ob, float* __restrict__ out) {
    int b = blockIdx.x, t = threadIdx.x;
    float p = r2[b * DD + t] * ow[t];
    __shared__ float sm[8];
    float s = p;
#pragma unroll
    for (int o = 16; o; o >>= 1) s += __shfl_xor_sync(0xffffffffu, s, o);
    if ((t & 31) == 0) sm[t >> 5] = s;
    __syncthreads();
    if (t == 0) {
        float tot = 0.f;
#pragma unroll
        for (int i = 0; i < 8; i++) tot += sm[i];
        out[b] = 0.5f * tot + ob[0];
    }
}

// ================================================================ host orchestration
extern "C" void kernel_launch(void* const* d_in, const int* in_sizes, int n_in,
                              void* d_out, int out_size) {
    const float* x   = (const float*)d_in[0];
    const float* cw  = (const float*)d_in[1];
    const float* cb  = (const float*)d_in[2];
    const float* bg  = (const float*)d_in[3];
    const float* bbn = (const float*)d_in[4];
    const float* pe  = (const float*)d_in[5];
    const float* qW  = (const float*)d_in[6];
    const float* qb  = (const float*)d_in[7];
    const float* kW  = (const float*)d_in[8];
    const float* kb  = (const float*)d_in[9];
    const float* vW  = (const float*)d_in[10];
    const float* vb  = (const float*)d_in[11];
    const float* oW  = (const float*)d_in[12];
    const float* ob  = (const float*)d_in[13];
    const float* scale = (const float*)d_in[14];
    const float* td  = (const float*)d_in[15];
    const float* ln1g = (const float*)d_in[16];
    const float* ln1b = (const float*)d_in[17];
    const float* f1W = (const float*)d_in[18];
    const float* f1b = (const float*)d_in[19];
    const float* f2W = (const float*)d_in[20];
    const float* f2b = (const float*)d_in[21];
    const float* ln2g = (const float*)d_in[22];
    const float* ln2b = (const float*)d_in[23];
    const float* outW = (const float*)d_in[24];
    const float* outb = (const float*)d_in[25];
    float* out = (float*)d_out;

    float* buf = nullptr;
    cudaGetSymbolAddress((void**)&buf, g_buf);
    float* H0   = buf;
    float* H2   = buf + 1L * NH;
    float* Qb   = buf + 2L * NH;
    float* Kb   = buf + 3L * NH;
    float* Vb   = buf + 4L * NH;
    float* CTX  = buf + 5L * NH;
    float* T    = buf + 6L * NH;
    float* FF   = buf + 7L * NH;
    float* TAIL = buf + 7L * NH + NFF;
    float* SM   = TAIL + 512;
    float* Q2    = SM + 0;     // 512
    float* CTX2  = SM + 512;   // 512
    float* T2    = SM + 1024;  // 512
    float* R1    = SM + 1536;  // 512
    float* FFROW = SM + 2048;  // 2048
    float* T3    = SM + 4096;  // 512
    float* R2    = SM + 4608;  // 512

    const int M = BB * SEQL;                // 4096
    dim3 gN256(DD / 64, M / 64);            // (4, 64)
    dim3 gN1024(DFFN / 64, M / 64);         // (16, 64)
    dim3 gAttn(SEQL / 128, BB * HH);        // (16, 16)

    // --- stem ---
    conv_pe_kernel<<<(NH + 255) / 256, 256>>>(x, cw, cb, bg, bbn, pe, H0);

    // --- layer 0 (full) ---
    gemm_kernel<false><<<gN256, 256>>>(H0, qW, qb, Qb, M, DD, DD);
    gemm_kernel<false><<<gN256, 256>>>(H0, kW, kb, Kb, M, DD, DD);
    gemm_kernel<false><<<gN256, 256>>>(H0, vW, vb, Vb, M, DD, DD);
    tailv_kernel<<<BB * HH, 256>>>(Vb, td, TAIL, 0);
    attn_kernel<<<gAttn, 128>>>(Qb, Kb, Vb, td, scale, TAIL, CTX, 0);
    gemm_kernel<false><<<gN256, 256>>>(CTX, oW, ob, T, M, DD, DD);
    ln_kernel<<<M, 256>>>(T, DD, H0, DD, ln1g, ln1b, H2, DD);
    gemm_kernel<true ><<<gN1024, 256>>>(H2, f1W, f1b, FF, M, DFFN, DD);
    gemm_kernel<false><<<gN256, 256>>>(FF, f2W, f2b, T, M, DD, DFFN);
    ln_kernel<<<M, 256>>>(T, DD, H2, DD, ln2g, ln2b, H0, DD);

    // --- layer 1 (only last token needed downstream of attention) ---
    const float* qW1 = qW + DD * DD;   const float* qb1 = qb + DD;
    const float* kW1 = kW + DD * DD;   const float* kb1 = kb + DD;
    const float* vW1 = vW + DD * DD;   const float* vb1 = vb + DD;
    const float* oW1 = oW + DD * DD;   const float* ob1 = ob + DD;
    const float* ln1g1 = ln1g + DD;    const float* ln1b1 = ln1b + DD;
    const float* ln2g1 = ln2g + DD;    const float* ln2b1 = ln2b + DD;
    const float* f1W1 = f1W + DFFN * DD; const float* f1b1 = f1b + DFFN;
    const float* f2W1 = f2W + DD * DFFN; const float* f2b1 = f2b + DD;
    const float* hlast = H0 + (long)(SEQL - 1) * DD;   // rows stride SEQL*DD

    gemm_kernel<false><<<gN256, 256>>>(H0, kW1, kb1, Kb, M, DD, DD);
    gemm_kernel<false><<<gN256, 256>>>(H0, vW1, vb1, Vb, M, DD, DD);
    tailv_kernel<<<BB * HH, 256>>>(Vb, td, TAIL, 1);

    rowgemm_kernel<false><<<dim3(BB, 1), 256, DD * 4>>>(hlast, (long)SEQL * DD, qW1, qb1, Q2, DD, DD);
    attn1_kernel<<<BB * HH, 128>>>(Q2, Kb, Vb, td, scale, TAIL, CTX2, 1);
    rowgemm_kernel<false><<<dim3(BB, 1), 256, DD * 4>>>(CTX2, DD, oW1, ob1, T2, DD, DD);
    ln_kernel<<<BB, 256>>>(T2, DD, hlast, (long)SEQL * DD, ln1g1, ln1b1, R1, DD);
    rowgemm_kernel<true ><<<dim3(BB, DFFN / 256), 256, DD * 4>>>(R1, DD, f1W1, f1b1, FFROW, DD, DFFN);
    rowgemm_kernel<false><<<dim3(BB, 1), 256, DFFN * 4>>>(FFROW, DFFN, f2W1, f2b1, T3, DFFN, DD);
    ln_kernel<<<BB, 256>>>(T3, DD, R1, DD, ln2g1, ln2b1, R2, DD);

    out_kernel<<<BB, 256>>>(R2, outW, outb, out);
}

// round 2
// speedup vs baseline: 1.1830x; 1.1830x over previous
#include <cuda_runtime.h>

#define BB 2
#define SEQL 2048
#define DD 256
#define HH 8
#define DKK 32
#define DFFN 1024
#define LL 2
#define EPSF 1e-5f

#define NH  (BB*SEQL*DD)      /* 1048576 */
#define NFF (BB*SEQL*DFFN)    /* 4194304 */

__device__ float g_buf[7L*NH + NFF + 512 + 8192];

__device__ __forceinline__ int compute_kcut(float tdh) {
    if (!(tdh > 1e-6f)) return SEQL;
    float c = 128.0f / tdh;
    if (c >= (float)SEQL) return SEQL;
    int k = (int)ceilf(c);
    return k < SEQL ? k : SEQL;
}

// ---------------------------------------------------------------- conv + bn + relu + pe
__global__ void conv_pe_kernel(const float* __restrict__ x, const float* __restrict__ cw,
                               const float* __restrict__ cb, const float* __restrict__ bg,
                               const float* __restrict__ bb, const float* __restrict__ pe,
                               float* __restrict__ out) {
    int idx = blockIdx.x * 256 + threadIdx.x;
    if (idx >= NH) return;
    int d = idx & (DD - 1);
    int t = (idx >> 8) & (SEQL - 1);
    int b = idx >> 19;
    const float* xb = x + b * SEQL;
    float xm = t > 0 ? xb[t - 1] : 0.f;
    float x0 = xb[t];
    float xp = (t < SEQL - 1) ? xb[t + 1] : 0.f;
    float v = cw[d * 3 + 0] * xm + cw[d * 3 + 1] * x0 + cw[d * 3 + 2] * xp + cb[d];
    v = v * rsqrtf(1.f + EPSF) * bg[d] + bb[d];
    v = fmaxf(v, 0.f);
    out[idx] = v + pe[t * DD + d];
}

// ---------------------------------------------------------------- SGEMM 64x64x16, double-buffered, 4x4 micro
// C(MxN) = A(MxK) * W(NxK)^T + bias ; K % 16 == 0, M,N % 64 == 0
template <bool RELU>
__global__ __launch_bounds__(256)
void gemm_kernel(const float* __restrict__ A, const float* __restrict__ W,
                 const float* __restrict__ bias, float* __restrict__ C,
                 int M, int N, int K) {
    __shared__ float As[2][16][68];
    __shared__ float Bs[2][16][68];
    const int tid = threadIdx.x;
    const int m0 = blockIdx.y * 64, n0 = blockIdx.x * 64;
    const int lr = tid >> 2;    // 0..63: tile row being loaded
    const int kq = tid & 3;     // 0..3 : k-quad
    const int tx = tid & 15, ty = tid >> 4;   // compute: 16 x 16 threads

    const float* Ap = A + (long)(m0 + lr) * K + kq * 4;
    const float* Bp = W + (long)(n0 + lr) * K + kq * 4;

    float4 pa = *(const float4*)(Ap);
    float4 pb = *(const float4*)(Bp);

    float acc[4][4];
#pragma unroll
    for (int i = 0; i < 4; i++)
#pragma unroll
        for (int j = 0; j < 4; j++) acc[i][j] = 0.f;

    As[0][kq * 4 + 0][lr] = pa.x; As[0][kq * 4 + 1][lr] = pa.y;
    As[0][kq * 4 + 2][lr] = pa.z; As[0][kq * 4 + 3][lr] = pa.w;
    Bs[0][kq * 4 + 0][lr] = pb.x; Bs[0][kq * 4 + 1][lr] = pb.y;
    Bs[0][kq * 4 + 2][lr] = pb.z; Bs[0][kq * 4 + 3][lr] = pb.w;
    __syncthreads();

    int s = 0;
    for (int k0 = 16;; k0 += 16) {
        const bool more = (k0 < K);
        if (more) {
            pa = *(const float4*)(Ap + k0);
            pb = *(const float4*)(Bp + k0);
        }
#pragma unroll
        for (int kk = 0; kk < 16; ++kk) {
            float4 av = *(const float4*)&As[s][kk][ty * 4];
            float4 bv = *(const float4*)&Bs[s][kk][tx * 4];
            acc[0][0] = fmaf(av.x, bv.x, acc[0][0]); acc[0][1] = fmaf(av.x, bv.y, acc[0][1]);
            acc[0][2] = fmaf(av.x, bv.z, acc[0][2]); acc[0][3] = fmaf(av.x, bv.w, acc[0][3]);
            acc[1][0] = fmaf(av.y, bv.x, acc[1][0]); acc[1][1] = fmaf(av.y, bv.y, acc[1][1]);
            acc[1][2] = fmaf(av.y, bv.z, acc[1][2]); acc[1][3] = fmaf(av.y, bv.w, acc[1][3]);
            acc[2][0] = fmaf(av.z, bv.x, acc[2][0]); acc[2][1] = fmaf(av.z, bv.y, acc[2][1]);
            acc[2][2] = fmaf(av.z, bv.z, acc[2][2]); acc[2][3] = fmaf(av.z, bv.w, acc[2][3]);
            acc[3][0] = fmaf(av.w, bv.x, acc[3][0]); acc[3][1] = fmaf(av.w, bv.y, acc[3][1]);
            acc[3][2] = fmaf(av.w, bv.z, acc[3][2]); acc[3][3] = fmaf(av.w, bv.w, acc[3][3]);
        }
        if (!more) break;
        const int ns = s ^ 1;
        As[ns][kq * 4 + 0][lr] = pa.x; As[ns][kq * 4 + 1][lr] = pa.y;
        As[ns][kq * 4 + 2][lr] = pa.z; As[ns][kq * 4 + 3][lr] = pa.w;
        Bs[ns][kq * 4 + 0][lr] = pb.x; Bs[ns][kq * 4 + 1][lr] = pb.y;
        Bs[ns][kq * 4 + 2][lr] = pb.z; Bs[ns][kq * 4 + 3][lr] = pb.w;
        __syncthreads();
        s = ns;
    }

    float b0 = bias[n0 + tx * 4 + 0], b1 = bias[n0 + tx * 4 + 1];
    float b2 = bias[n0 + tx * 4 + 2], b3 = bias[n0 + tx * 4 + 3];
#pragma unroll
    for (int i = 0; i < 4; ++i) {
        float4 v;
        v.x = acc[i][0] + b0; v.y = acc[i][1] + b1;
        v.z = acc[i][2] + b2; v.w = acc[i][3] + b3;
        if (RELU) {
            v.x = fmaxf(v.x, 0.f); v.y = fmaxf(v.y, 0.f);
            v.z = fmaxf(v.z, 0.f); v.w = fmaxf(v.w, 0.f);
        }
        *(float4*)(C + (long)(m0 + ty * 4 + i) * N + n0 + tx * 4) = v;
    }
}

// ---------------------------------------------------------------- tail-V: sum_{k>=kcut} v[b,k,h*32+d]  (1024 thr, MLP4)
__global__ __launch_bounds__(1024)
void tailv_kernel(const float* __restrict__ V, const float* __restrict__ td,
                  float* __restrict__ tailV, int l) {
    int b = blockIdx.x / HH, h = blockIdx.x % HH;
    float tdh = td[l * HH + h];
    int kcut = compute_kcut(tdh);
    int d = threadIdx.x & 31, kg = threadIdx.x >> 5;   // 32 k-groups
    long base = (long)b * SEQL * DD + h * DKK + d;
    float s0 = 0.f, s1 = 0.f, s2 = 0.f, s3 = 0.f;
    int k = kcut + kg;
    for (; k + 96 < SEQL; k += 128) {
        s0 += V[base + (long)(k      ) * DD];
        s1 += V[base + (long)(k +  32) * DD];
        s2 += V[base + (long)(k +  64) * DD];
        s3 += V[base + (long)(k +  96) * DD];
    }
    for (; k < SEQL; k += 32) s0 += V[base + (long)k * DD];
    float s = (s0 + s1) + (s2 + s3);
    __shared__ float sm[32][33];
    sm[kg][d] = s;
    __syncthreads();
    if (kg == 0) {
        float t = 0.f;
#pragma unroll
        for (int i = 0; i < 32; i++) t += sm[i][d];
        tailV[blockIdx.x * DKK + d] = t;
    }
}

// ---------------------------------------------------------------- attention (all queries), kcut-truncated
__global__ __launch_bounds__(128)
void attn_kernel(const float* __restrict__ Q, const float* __restrict__ Km,
                 const float* __restrict__ Vm, const float* __restrict__ td,
                 const float* __restrict__ scale, const float* __restrict__ tailV,
                 float* __restrict__ ctx, int l) {
    __shared__ float Ks[128][DKK];
    __shared__ float Vs[128][DKK];
    __shared__ float dec[128];
    int bh = blockIdx.y;
    int b = bh / HH, h = bh % HH;
    int tid = threadIdx.x;
    int q = blockIdx.x * 128 + tid;
    float tdh = td[l * HH + h];
    int kcut = compute_kcut(tdh);
    float c = scale[l] * rsqrtf((float)DKK);
    float4 qv[8];
    {
        const float4* qp = (const float4*)(Q + ((long)(b * SEQL + q)) * DD + h * DKK);
#pragma unroll
        for (int j = 0; j < 8; ++j) {
            float4 t = qp[j];
            t.x *= c; t.y *= c; t.z *= c; t.w *= c;
            qv[j] = t;
        }
    }
    float Z = 0.f;
    float4 cx[8];
#pragma unroll
    for (int j = 0; j < 8; ++j) cx[j] = make_float4(0.f, 0.f, 0.f, 0.f);

    for (int kb = 0; kb < kcut; kb += 128) {
        int kn = min(128, kcut - kb);
        __syncthreads();
        const float4* Kg = (const float4*)(Km + ((long)(b * SEQL + kb)) * DD + h * DKK);
        const float4* Vg = (const float4*)(Vm + ((long)(b * SEQL + kb)) * DD + h * DKK);
#pragma unroll
        for (int i = 0; i < 8; i++) {
            int idx = i * 128 + tid;                    // over 1024 float4 slots
            int r = idx >> 3, c4 = idx & 7;
            if (r < kn) {
                ((float4*)Ks[r])[c4] = Kg[(long)r * (DD / 4) + c4];
                ((float4*)Vs[r])[c4] = Vg[(long)r * (DD / 4) + c4];
            }
        }
        if (tid < kn) dec[tid] = __expf(-tdh * (float)(kb + tid));
        __syncthreads();
        for (int kk = 0; kk < kn; ++kk) {
            const float4* kr = (const float4*)Ks[kk];
            float s0 = 0.f, s1 = 0.f, s2 = 0.f, s3 = 0.f;
#pragma unroll
            for (int j = 0; j < 8; j += 2) {
                float4 k0 = kr[j], k1 = kr[j + 1];
                s0 = fmaf(qv[j].x, k0.x, s0); s1 = fmaf(qv[j].y, k0.y, s1);
                s2 = fmaf(qv[j].z, k0.z, s2); s3 = fmaf(qv[j].w, k0.w, s3);
                s0 = fmaf(qv[j + 1].x, k1.x, s0); s1 = fmaf(qv[j + 1].y, k1.y, s1);
                s2 = fmaf(qv[j + 1].z, k1.z, s2); s3 = fmaf(qv[j + 1].w, k1.w, s3);
            }
            float s = ((s0 + s1) + (s2 + s3)) * dec[kk];
            float e = __expf(s);
            float w = e * e / (1.f + e);        // e * sigmoid(s)
            Z += e;
            const float4* vr = (const float4*)Vs[kk];
#pragma unroll
            for (int j = 0; j < 8; ++j) {
                float4 vv = vr[j];
                cx[j].x = fmaf(w, vv.x, cx[j].x);
                cx[j].y = fmaf(w, vv.y, cx[j].y);
                cx[j].z = fmaf(w, vv.z, cx[j].z);
                cx[j].w = fmaf(w, vv.w, cx[j].w);
            }
        }
    }
    Z += (float)(SEQL - kcut);
    float invZ = 1.f / Z;
    const float4* tv = (const float4*)(tailV + bh * DKK);
    float4* op = (float4*)(ctx + ((long)(b * SEQL + q)) * DD + h * DKK);
#pragma unroll
    for (int j = 0; j < 8; ++j) {
        float4 t = tv[j];
        float4 o;
        o.x = (cx[j].x + 0.5f * t.x) * invZ;
        o.y = (cx[j].y + 0.5f * t.y) * invZ;
        o.z = (cx[j].z + 0.5f * t.z) * invZ;
        o.w = (cx[j].w + 0.5f * t.w) * invZ;
        op[j] = o;
    }
}

// ---------------------------------------------------------------- single-query attention (layer 2 last token)
__global__ __launch_bounds__(128)
void attn1_kernel(const float* __restrict__ q2, const float* __restrict__ Km,
                  const float* __restrict__ Vm, const float* __restrict__ td,
                  const float* __restrict__ scale, const float* __restrict__ tailV,
                  float* __restrict__ ctx2, int l) {
    int b = blockIdx.x / HH, h = blockIdx.x % HH;
    int tid = threadIdx.x;
    float tdh = td[l * HH + h];
    int kcut = compute_kcut(tdh);
    float c = scale[l] * rsqrtf((float)DKK);
    __shared__ float qs[DKK];
    __shared__ float ws[128];
    __shared__ float red[4];
    if (tid < DKK) qs[tid] = q2[b * DD + h * DKK + tid] * c;
    __syncthreads();
    float Zp = 0.f;
    float cxd = 0.f;
    for (int kb = 0; kb < kcut; kb += 128) {
        int kn = min(128, kcut - kb);
        float w = 0.f;
        if (tid < kn) {
            int k = kb + tid;
            const float* kr = Km + ((long)(b * SEQL + k)) * DD + h * DKK;
            float s = 0.f;
#pragma unroll
            for (int d = 0; d < DKK; ++d) s = fmaf(qs[d], kr[d], s);
            s *= __expf(-tdh * (float)k);
            float e = __expf(s);
            w = e * e / (1.f + e);
            Zp += e;
        }
        __syncthreads();
        ws[tid] = w;
        __syncthreads();
        if (tid < DKK) {
            for (int kk = 0; kk < kn; ++kk)
                cxd = fmaf(ws[kk], Vm[((long)(b * SEQL + kb + kk)) * DD + h * DKK + tid], cxd);
        }
        __syncthreads();
    }
    float s = Zp;
#pragma unroll
    for (int o = 16; o; o >>= 1) s += __shfl_xor_sync(0xffffffffu, s, o);
    if ((tid & 31) == 0) red[tid >> 5] = s;
    __syncthreads();
    float Z = red[0] + red[1] + red[2] + red[3] + (float)(SEQL - kcut);
    if (tid < DKK)
        ctx2[b * DD + h * DKK + tid] = (cxd + 0.5f * tailV[blockIdx.x * DKK + tid]) / Z;
}

// ---------------------------------------------------------------- small-M GEMM (M=2 rows)
template <bool RELU>
__global__ void rowgemm_kernel(const float* __restrict__ A, long lda,
                               const float* __restrict__ W, const float* __restrict__ bias,
                               float* __restrict__ C, int K, int N) {
    extern __shared__ float arow[];
    int m = blockIdx.x;
    int n = blockIdx.y * blockDim.x + threadIdx.x;
    for (int i = threadIdx.x; i < K; i += blockDim.x) arow[i] = A[(long)m * lda + i];
    __syncthreads();
    float s = bias[n];
    const float* wr = W + (long)n * K;
#pragma unroll 4
    for (int kk = 0; kk < K; ++kk) s = fmaf(arow[kk], wr[kk], s);
    if (RELU) s = fmaxf(s, 0.f);
    C[(long)m * N + n] = s;
}

// ---------------------------------------------------------------- residual + layernorm (one row per block, D=256)
__global__ void ln_kernel(const float* __restrict__ z, long zs,
                          const float* __restrict__ res, long rs,
                          const float* __restrict__ g, const float* __restrict__ be,
                          float* __restrict__ out, long os) {
    int m = blockIdx.x, t = threadIdx.x;
    float v = z[(long)m * zs + t] + res[(long)m * rs + t];
    __shared__ float sm[8];
    float s = v;
#pragma unroll
    for (int o = 16; o; o >>= 1) s += __shfl_xor_sync(0xffffffffu, s, o);
    if ((t & 31) == 0) sm[t >> 5] = s;
    __syncthreads();
    float tot = 0.f;
#pragma unroll
    for (int i = 0; i < 8; i++) tot += sm[i];
    float mean = tot * (1.0f / DD);
    float dv = v - mean;
    float s2 = dv * dv;
    __syncthreads();
#pragma unroll
    for (int o = 16; o; o >>= 1) s2 += __shfl_xor_sync(0xffffffffu, s2, o);
    if ((t & 31) == 0) sm[t >> 5] = s2;
    __syncthreads();
    float var = 0.f;
#pragma unroll
    for (int i = 0; i < 8; i++) var += sm[i];
    var *= (1.0f / DD);
    out[(long)m * os + t] = dv * rsqrtf(var + EPSF) * g[t] + be[t];
}

// ---------------------------------------------------------------- final projection
__global__ void out_kernel(const float* __restrict__ r2, const float* __restrict__ ow,
                           const float* __restrict__ ob, float* __restrict__ out) {
    int b = blockIdx.x, t = threadIdx.x;
    float p = r2[b * DD + t] * ow[t];
    __shared__ float sm[8];
    float s = p;
#pragma unroll
    for (int o = 16; o; o >>= 1) s += __shfl_xor_sync(0xffffffffu, s, o);
    if ((t & 31) == 0) sm[t >> 5] = s;
    __syncthreads();
    if (t == 0) {
        float tot = 0.f;
#pragma unroll
        for (int i = 0; i < 8; i++) tot += sm[i];
        out[b] = 0.5f * tot + ob[0];
    }
}

// ================================================================ host orchestration
extern "C" void kernel_launch(void* const* d_in, const int* in_sizes, int n_in,
                              void* d_out, int out_size) {
    const float* x   = (const float*)d_in[0];
    const float* cw  = (const float*)d_in[1];
    const float* cb  = (const float*)d_in[2];
    const float* bg  = (const float*)d_in[3];
    const float* bbn = (const float*)d_in[4];
    const float* pe  = (const float*)d_in[5];
    const float* qW  = (const float*)d_in[6];
    const float* qb  = (const float*)d_in[7];
    const float* kW  = (const float*)d_in[8];
    const float* kb  = (const float*)d_in[9];
    const float* vW  = (const float*)d_in[10];
    const float* vb  = (const float*)d_in[11];
    const float* oW  = (const float*)d_in[12];
    const float* ob  = (const float*)d_in[13];
    const float* scale = (const float*)d_in[14];
    const float* td  = (const float*)d_in[15];
    const float* ln1g = (const float*)d_in[16];
    const float* ln1b = (const float*)d_in[17];
    const float* f1W = (const float*)d_in[18];
    const float* f1b = (const float*)d_in[19];
    const float* f2W = (const float*)d_in[20];
    const float* f2b = (const float*)d_in[21];
    const float* ln2g = (const float*)d_in[22];
    const float* ln2b = (const float*)d_in[23];
    const float* outW = (const float*)d_in[24];
    const float* outb = (const float*)d_in[25];
    float* out = (float*)d_out;

    float* buf = nullptr;
    cudaGetSymbolAddress((void**)&buf, g_buf);
    float* H0   = buf;
    float* H2   = buf + 1L * NH;
    float* Qb   = buf + 2L * NH;
    float* Kb   = buf + 3L * NH;
    float* Vb   = buf + 4L * NH;
    float* CTX  = buf + 5L * NH;
    float* T    = buf + 6L * NH;
    float* FF   = buf + 7L * NH;
    float* TAIL = buf + 7L * NH + NFF;
    float* SM   = TAIL + 512;
    float* Q2    = SM + 0;
    float* CTX2  = SM + 512;
    float* T2    = SM + 1024;
    float* R1    = SM + 1536;
    float* FFROW = SM + 2048;
    float* T3    = SM + 4096;
    float* R2    = SM + 4608;

    const int M = BB * SEQL;                 // 4096
    dim3 gN256(DD / 64, M / 64);             // (4, 64)
    dim3 gN1024(DFFN / 64, M / 64);          // (16, 64)
    dim3 gAttn(SEQL / 128, BB * HH);         // (16, 16)

    // --- stem ---
    conv_pe_kernel<<<(NH + 255) / 256, 256>>>(x, cw, cb, bg, bbn, pe, H0);

    // --- layer 0 (full) ---
    gemm_kernel<false><<<gN256, 256>>>(H0, qW, qb, Qb, M, DD, DD);
    gemm_kernel<false><<<gN256, 256>>>(H0, kW, kb, Kb, M, DD, DD);
    gemm_kernel<false><<<gN256, 256>>>(H0, vW, vb, Vb, M, DD, DD);
    tailv_kernel<<<BB * HH, 1024>>>(Vb, td, TAIL, 0);
    attn_kernel<<<gAttn, 128>>>(Qb, Kb, Vb, td, scale, TAIL, CTX, 0);
    gemm_kernel<false><<<gN256, 256>>>(CTX, oW, ob, T, M, DD, DD);
    ln_kernel<<<M, 256>>>(T, DD, H0, DD, ln1g, ln1b, H2, DD);
    gemm_kernel<true ><<<gN1024, 256>>>(H2, f1W, f1b, FF, M, DFFN, DD);
    gemm_kernel<false><<<gN256, 256>>>(FF, f2W, f2b, T, M, DD, DFFN);
    ln_kernel<<<M, 256>>>(T, DD, H2, DD, ln2g, ln2b, H0, DD);

    // --- layer 1 (only last token needed downstream of attention) ---
    const float* qW1 = qW + DD * DD;   const float* qb1 = qb + DD;
    const float* kW1 = kW + DD * DD;   const float* kb1 = kb + DD;
    const float* vW1 = vW + DD * DD;   const float* vb1 = vb + DD;
    const float* oW1 = oW + DD * DD;   const float* ob1 = ob + DD;
    const float* ln1g1 = ln1g + DD;    const float* ln1b1 = ln1b + DD;
    const float* ln2g1 = ln2g + DD;    const float* ln2b1 = ln2b + DD;
    const float* f1W1 = f1W + DFFN * DD; const float* f1b1 = f1b + DFFN;
    const float* f2W1 = f2W + DD * DFFN; const float* f2b1 = f2b + DD;
    const float* hlast = H0 + (long)(SEQL - 1) * DD;

    gemm_kernel<false><<<gN256, 256>>>(H0, kW1, kb1, Kb, M, DD, DD);
    gemm_kernel<false><<<gN256, 256>>>(H0, vW1, vb1, Vb, M, DD, DD);
    tailv_kernel<<<BB * HH, 1024>>>(Vb, td, TAIL, 1);

    rowgemm_kernel<false><<<dim3(BB, 1), 256, DD * 4>>>(hlast, (long)SEQL * DD, qW1, qb1, Q2, DD, DD);
    attn1_kernel<<<BB * HH, 128>>>(Q2, Kb, Vb, td, scale, TAIL, CTX2, 1);
    rowgemm_kernel<false><<<dim3(BB, 1), 256, DD * 4>>>(CTX2, DD, oW1, ob1, T2, DD, DD);
    ln_kernel<<<BB, 256>>>(T2, DD, hlast, (long)SEQL * DD, ln1g1, ln1b1, R1, DD);
    rowgemm_kernel<true ><<<dim3(BB, DFFN / 256), 256, DD * 4>>>(R1, DD, f1W1, f1b1, FFROW, DD, DFFN);
    rowgemm_kernel<false><<<dim3(BB, 1), 256, DFFN * 4>>>(FFROW, DFFN, f2W1, f2b1, T3, DFFN, DD);
    ln_kernel<<<BB, 256>>>(T3, DD, R1, DD, ln2g1, ln2b1, R2, DD);

    out_kernel<<<BB, 256>>>(R2, outW, outb, out);
}